// round 16
// baseline (speedup 1.0000x reference)
#include <cuda_runtime.h>
#include <cuda_bf16.h>

#define FEAT 1024
#define NREF 4
#define WPB 16           // warps per block (512 threads)
#define TPB (WPB * 32)
#define ROWS_PER_BLOCK (WPB * 2)

// Fused single kernel (R14-proven body): stage RAW vectors into SMEM and fold
// normalization into the per-reflection scalar s = (-2/||v||^2) * dot.
// Body: 2 rows/warp, sequential reflections, v regs shared across rows,
// interleaved shfl butterflies, plain vectorized global loads/stores.
// This round: 512-thread blocks — halves prologue replication + wave count,
// doubles warps/SM to 32 so new-CTA prologues hide behind the co-resident CTA.
__global__ __launch_bounds__(TPB, 2) void householder_apply_kernel(
    const float* __restrict__ x, const float* __restrict__ vecs,
    float* __restrict__ out, int batch) {
    __shared__ float sv[NREF][FEAT];     // raw (unnormalized) vectors
    __shared__ float s_nred[NREF][WPB];  // per-warp ||v||^2 partials
    __shared__ float s_scale[NREF];      // -2 / ||v||^2

    int tid = threadIdx.x;
    int warp = tid >> 5;
    int lane = tid & 31;

    // ---- Stage vectors to SMEM and compute -2/||v||^2 in the same pass ----
    // 256 float4 per vector; threads 0..255 stage, the rest contribute zeros.
    {
        float ss[NREF];
        if (tid < FEAT / 4) {
#pragma unroll
            for (int k = 0; k < NREF; k++) {
                float4 r = ((const float4*)(vecs + k * FEAT))[tid];
                ((float4*)sv[k])[tid] = r;
                ss[k] = r.x * r.x + r.y * r.y + r.z * r.z + r.w * r.w;
            }
        } else {
#pragma unroll
            for (int k = 0; k < NREF; k++) ss[k] = 0.f;
        }
#pragma unroll
        for (int o = 16; o; o >>= 1)
#pragma unroll
            for (int k = 0; k < NREF; k++) ss[k] += __shfl_xor_sync(0xffffffffu, ss[k], o);
        if (lane == 0)
#pragma unroll
            for (int k = 0; k < NREF; k++) s_nred[k][warp] = ss[k];
        __syncthreads();
        if (tid < NREF) {
            float tot = 0.f;
#pragma unroll
            for (int w = 0; w < WPB; w++) tot += s_nred[tid][w];
            s_scale[tid] = -2.f / tot;
        }
        __syncthreads();
    }

    float scale[NREF];
#pragma unroll
    for (int k = 0; k < NREF; k++) scale[k] = s_scale[k];

    long long rowA = (long long)blockIdx.x * ROWS_PER_BLOCK + warp;
    long long rowB = rowA + WPB;
    bool hasA = rowA < batch;
    bool hasB = rowB < batch;

    const float4* xa = (const float4*)(x + rowA * (long long)FEAT);
    const float4* xb = (const float4*)(x + rowB * (long long)FEAT);
    float4 ya[8], yb[8];
    if (hasA) {
#pragma unroll
        for (int j = 0; j < 8; j++) ya[j] = xa[j * 32 + lane];
    }
    if (hasB) {
#pragma unroll
        for (int j = 0; j < 8; j++) yb[j] = xb[j * 32 + lane];
    }

#pragma unroll
    for (int k = 0; k < NREF; k++) {
        const float4* vp = (const float4*)sv[k];
        float4 vv[8];
        float da = 0.f, db = 0.f;
#pragma unroll
        for (int j = 0; j < 8; j++) {
            vv[j] = vp[j * 32 + lane];
            da = fmaf(ya[j].x, vv[j].x, da);
            da = fmaf(ya[j].y, vv[j].y, da);
            da = fmaf(ya[j].z, vv[j].z, da);
            da = fmaf(ya[j].w, vv[j].w, da);
            db = fmaf(yb[j].x, vv[j].x, db);
            db = fmaf(yb[j].y, vv[j].y, db);
            db = fmaf(yb[j].z, vv[j].z, db);
            db = fmaf(yb[j].w, vv[j].w, db);
        }
        // Two independent butterflies, interleaved so latencies overlap.
#pragma unroll
        for (int o = 16; o; o >>= 1) {
            da += __shfl_xor_sync(0xffffffffu, da, o);
            db += __shfl_xor_sync(0xffffffffu, db, o);
        }
        float sa = scale[k] * da;
        float sb = scale[k] * db;
#pragma unroll
        for (int j = 0; j < 8; j++) {
            ya[j].x = fmaf(sa, vv[j].x, ya[j].x);
            ya[j].y = fmaf(sa, vv[j].y, ya[j].y);
            ya[j].z = fmaf(sa, vv[j].z, ya[j].z);
            ya[j].w = fmaf(sa, vv[j].w, ya[j].w);
            yb[j].x = fmaf(sb, vv[j].x, yb[j].x);
            yb[j].y = fmaf(sb, vv[j].y, yb[j].y);
            yb[j].z = fmaf(sb, vv[j].z, yb[j].z);
            yb[j].w = fmaf(sb, vv[j].w, yb[j].w);
        }
    }

    if (hasA) {
        float4* oa = (float4*)(out + rowA * (long long)FEAT);
#pragma unroll
        for (int j = 0; j < 8; j++) oa[j * 32 + lane] = ya[j];
    }
    if (hasB) {
        float4* ob = (float4*)(out + rowB * (long long)FEAT);
#pragma unroll
        for (int j = 0; j < 8; j++) ob[j * 32 + lane] = yb[j];
    }
}

extern "C" void kernel_launch(void* const* d_in, const int* in_sizes, int n_in,
                              void* d_out, int out_size) {
    const float* x = (const float*)d_in[0];       // (BATCH, 1024) fp32
    const float* vectors = (const float*)d_in[1]; // (4, 1024) fp32
    float* out = (float*)d_out;
    int batch = in_sizes[0] / FEAT;

    int blocks = (batch + ROWS_PER_BLOCK - 1) / ROWS_PER_BLOCK;
    householder_apply_kernel<<<blocks, TPB>>>(x, vectors, out, batch);
}

// round 17
// speedup vs baseline: 3.3294x; 3.3294x over previous
#include <cuda_runtime.h>
#include <cuda_bf16.h>

#define FEAT 1024
#define NREF 4
#define WPB 8            // warps per block (256 threads — proven optimum)
#define TPB (WPB * 32)
#define ROWS_PER_BLOCK (WPB * 2)

// R14 final configuration (best measured: 83.7us wall / 79.6us kernel,
// DRAM 76.1%, HBM 6.03 TB/s). Fused single kernel: stage RAW vectors into
// SMEM and fold normalization into the per-reflection scalar
// s = (-2/||v||^2) * dot. Body: 2 rows/warp, sequential reflections, v regs
// shared across rows, interleaved shfl butterflies, plain vectorized
// 128-bit global loads/stores (cache-policy hints tested and rejected).
// NOTE: body requires ~126 regs; do NOT tighten launch bounds (512-thread /
// occupancy-forcing variants spill catastrophically — R16: 3.3x slower).
__global__ __launch_bounds__(TPB, 2) void householder_apply_kernel(
    const float* __restrict__ x, const float* __restrict__ vecs,
    float* __restrict__ out, int batch) {
    __shared__ float sv[NREF][FEAT];     // raw (unnormalized) vectors
    __shared__ float s_nred[NREF][WPB];  // per-warp ||v||^2 partials
    __shared__ float s_scale[NREF];      // -2 / ||v||^2

    int tid = threadIdx.x;
    int warp = tid >> 5;
    int lane = tid & 31;

    // ---- Stage vectors to SMEM and compute -2/||v||^2 in the same pass ----
    {
        float ss[NREF];
#pragma unroll
        for (int k = 0; k < NREF; k++) {
            float4 r = ((const float4*)(vecs + k * FEAT))[tid];  // 256 f4/vector
            ((float4*)sv[k])[tid] = r;
            ss[k] = r.x * r.x + r.y * r.y + r.z * r.z + r.w * r.w;
        }
#pragma unroll
        for (int o = 16; o; o >>= 1)
#pragma unroll
            for (int k = 0; k < NREF; k++) ss[k] += __shfl_xor_sync(0xffffffffu, ss[k], o);
        if (lane == 0)
#pragma unroll
            for (int k = 0; k < NREF; k++) s_nred[k][warp] = ss[k];
        __syncthreads();
        if (tid < NREF) {
            float tot = 0.f;
#pragma unroll
            for (int w = 0; w < WPB; w++) tot += s_nred[tid][w];
            s_scale[tid] = -2.f / tot;
        }
        __syncthreads();
    }

    float scale[NREF];
#pragma unroll
    for (int k = 0; k < NREF; k++) scale[k] = s_scale[k];

    long long rowA = (long long)blockIdx.x * ROWS_PER_BLOCK + warp;
    long long rowB = rowA + WPB;
    bool hasA = rowA < batch;
    bool hasB = rowB < batch;

    const float4* xa = (const float4*)(x + rowA * (long long)FEAT);
    const float4* xb = (const float4*)(x + rowB * (long long)FEAT);
    float4 ya[8], yb[8];
    if (hasA) {
#pragma unroll
        for (int j = 0; j < 8; j++) ya[j] = xa[j * 32 + lane];
    }
    if (hasB) {
#pragma unroll
        for (int j = 0; j < 8; j++) yb[j] = xb[j * 32 + lane];
    }

#pragma unroll
    for (int k = 0; k < NREF; k++) {
        const float4* vp = (const float4*)sv[k];
        float4 vv[8];
        float da = 0.f, db = 0.f;
#pragma unroll
        for (int j = 0; j < 8; j++) {
            vv[j] = vp[j * 32 + lane];
            da = fmaf(ya[j].x, vv[j].x, da);
            da = fmaf(ya[j].y, vv[j].y, da);
            da = fmaf(ya[j].z, vv[j].z, da);
            da = fmaf(ya[j].w, vv[j].w, da);
            db = fmaf(yb[j].x, vv[j].x, db);
            db = fmaf(yb[j].y, vv[j].y, db);
            db = fmaf(yb[j].z, vv[j].z, db);
            db = fmaf(yb[j].w, vv[j].w, db);
        }
        // Two independent butterflies, interleaved so latencies overlap.
#pragma unroll
        for (int o = 16; o; o >>= 1) {
            da += __shfl_xor_sync(0xffffffffu, da, o);
            db += __shfl_xor_sync(0xffffffffu, db, o);
        }
        float sa = scale[k] * da;
        float sb = scale[k] * db;
#pragma unroll
        for (int j = 0; j < 8; j++) {
            ya[j].x = fmaf(sa, vv[j].x, ya[j].x);
            ya[j].y = fmaf(sa, vv[j].y, ya[j].y);
            ya[j].z = fmaf(sa, vv[j].z, ya[j].z);
            ya[j].w = fmaf(sa, vv[j].w, ya[j].w);
            yb[j].x = fmaf(sb, vv[j].x, yb[j].x);
            yb[j].y = fmaf(sb, vv[j].y, yb[j].y);
            yb[j].z = fmaf(sb, vv[j].z, yb[j].z);
            yb[j].w = fmaf(sb, vv[j].w, yb[j].w);
        }
    }

    if (hasA) {
        float4* oa = (float4*)(out + rowA * (long long)FEAT);
#pragma unroll
        for (int j = 0; j < 8; j++) oa[j * 32 + lane] = ya[j];
    }
    if (hasB) {
        float4* ob = (float4*)(out + rowB * (long long)FEAT);
#pragma unroll
        for (int j = 0; j < 8; j++) ob[j * 32 + lane] = yb[j];
    }
}

extern "C" void kernel_launch(void* const* d_in, const int* in_sizes, int n_in,
                              void* d_out, int out_size) {
    const float* x = (const float*)d_in[0];       // (BATCH, 1024) fp32
    const float* vectors = (const float*)d_in[1]; // (4, 1024) fp32
    float* out = (float*)d_out;
    int batch = in_sizes[0] / FEAT;

    int blocks = (batch + ROWS_PER_BLOCK - 1) / ROWS_PER_BLOCK;
    householder_apply_kernel<<<blocks, TPB>>>(x, vectors, out, batch);
}